// round 8
// baseline (speedup 1.0000x reference)
#include <cuda_runtime.h>
#include <cstdint>

#define N_NODES   50000
#define N_EDGES   800000
#define IN_DIM    128     // 4*MUL
#define W_DIM     160     // 5*MUL
#define OUT_DIM   224     // 7*MUL
#define MUL       32

#define INV_SQRT3f 0.57735026918962576451f
#define INV_SQRT2f 0.70710678118654752440f

// vector reduction: red.global.add.v4.f32 (sm_90+)
__device__ __forceinline__ void red4(float* addr, float a, float b, float c, float d) {
    asm volatile("red.global.add.v4.f32 [%0], {%1, %2, %3, %4};"
                 :: "l"(addr), "f"(a), "f"(b), "f"(c), "f"(d)
                 : "memory");
}

// streaming (evict-first) 16B load: single-use data must not occupy L2
__device__ __forceinline__ float4 ldcs4(const float4* p) { return __ldcs(p); }

__global__ void zero_out_kernel(float4* __restrict__ out, int n4) {
    int i = blockIdx.x * blockDim.x + threadIdx.x;
    int stride = gridDim.x * blockDim.x;
    float4 z = make_float4(0.f, 0.f, 0.f, 0.f);
    for (; i < n4; i += stride) out[i] = z;
}

// One edge per 8 threads; thread t owns channels [4t, 4t+4). Non-persistent.
__global__ __launch_bounds__(256, 6)
void convtp_kernel(const float* __restrict__ nf,   // [N_NODES, 128]
                   const float* __restrict__ ang,  // [N_EDGES, 4]
                   const int* __restrict__ ei,     // [N_EDGES, 2] int32
                   const float* __restrict__ tw,   // [N_EDGES, 160]
                   float* __restrict__ out)        // [N_NODES, 224]
{
    int gid = blockIdx.x * blockDim.x + threadIdx.x;
    int e = gid >> 3;
    int t = gid & 7;
    if (e >= N_EDGES) return;

    // edge index — single-use stream, evict-first
    int2 se = __ldcs(((const int2*)ei) + e);
    int src = se.x;
    int dst = se.y;

    // angular — single-use stream, evict-first
    float4 y = ldcs4(((const float4*)ang) + e);
    const float y0  = y.x;
    const float y1x = y.y, y1y = y.z, y1z = y.w;

    // gather node features: default read-only caching (R3-proven best)
    const float4* hp = (const float4*)(nf + (long long)src * IN_DIM);
    float4 h0v = __ldg(hp + t);
    float4 hav = __ldg(hp + 8  + t);
    float4 hbv = __ldg(hp + 16 + t);
    float4 hcv = __ldg(hp + 24 + t);

    // weights — 512MB single-use stream, evict-first
    const float4* wp = (const float4*)(tw + (long long)e * W_DIM);
    float4 w0v = ldcs4(wp + t);
    float4 w1v = ldcs4(wp + 8  + t);
    float4 w2v = ldcs4(wp + 16 + t);
    float4 w3v = ldcs4(wp + 24 + t);
    float4 w4v = ldcs4(wp + 32 + t);

    const float* h0 = (const float*)&h0v;
    const float* ha = (const float*)&hav;
    const float* hb = (const float*)&hbv;
    const float* hc = (const float*)&hcv;
    const float* w0 = (const float*)&w0v;
    const float* w1 = (const float*)&w1v;
    const float* w2 = (const float*)&w2v;
    const float* w3 = (const float*)&w3v;
    const float* w4 = (const float*)&w4v;

    float r0[4], o1o0[4], o1o1[4], o1o2[4], o1e0[4], o1e1[4], o1e2[4];

    #pragma unroll
    for (int j = 0; j < 4; j++) {
        float H0 = h0[j];
        float A = ha[j], B = hb[j], C = hc[j];   // h1[0..2]
        float dot = A * y1x + B * y1y + C * y1z;

        r0[j]   = w0[j] * H0 * y0 + w3[j] * (INV_SQRT3f * dot);

        o1o0[j] = w1[j] * H0 * y1x + w2[j] * A * y0;
        o1o1[j] = w1[j] * H0 * y1y + w2[j] * B * y0;
        o1o2[j] = w1[j] * H0 * y1z + w2[j] * C * y0;

        float cr0 = B * y1z - C * y1y;
        float cr1 = C * y1x - A * y1z;
        float cr2 = A * y1y - B * y1x;
        float s = INV_SQRT2f;
        o1e0[j] = w4[j] * (s * cr0);
        o1e1[j] = w4[j] * (s * cr1);
        o1e2[j] = w4[j] * (s * cr2);
    }

    float* op = out + (long long)dst * OUT_DIM + 4 * t;
    red4(op,             r0[0],   r0[1],   r0[2],   r0[3]);
    red4(op + MUL,       o1o0[0], o1o0[1], o1o0[2], o1o0[3]);
    red4(op + 2 * MUL,   o1o1[0], o1o1[1], o1o1[2], o1o1[3]);
    red4(op + 3 * MUL,   o1o2[0], o1o2[1], o1o2[2], o1o2[3]);
    red4(op + 4 * MUL,   o1e0[0], o1e0[1], o1e0[2], o1e0[3]);
    red4(op + 5 * MUL,   o1e1[0], o1e1[1], o1e1[2], o1e1[3]);
    red4(op + 6 * MUL,   o1e2[0], o1e2[1], o1e2[2], o1e2[3]);
}

extern "C" void kernel_launch(void* const* d_in, const int* in_sizes, int n_in,
                              void* d_out, int out_size) {
    const float* nf  = (const float*)d_in[0];   // node_features
    const float* ang = (const float*)d_in[1];   // edge_angular
    const int*   ei  = (const int*)d_in[2];     // edge_index (int32)
    const float* tw  = (const float*)d_in[3];   // tp_weights
    float* out = (float*)d_out;

    // zero the (poisoned) output — vectorized
    int n4 = out_size / 4;
    int zgrid = (n4 + 255) / 256;
    if (zgrid > 2368) zgrid = 2368;
    zero_out_kernel<<<zgrid, 256>>>((float4*)out, n4);

    // main edge kernel: 8 threads per edge, 25000 CTAs
    long long total_threads = (long long)N_EDGES * 8;
    int block = 256;
    long long grid = (total_threads + block - 1) / block;
    convtp_kernel<<<(unsigned)grid, block>>>(nf, ang, ei, tw, out);
}

// round 9
// speedup vs baseline: 1.1662x; 1.1662x over previous
#include <cuda_runtime.h>
#include <cstdint>

#define N_NODES   50000
#define N_EDGES   800000
#define IN_DIM    128     // 4*MUL
#define W_DIM     160     // 5*MUL
#define OUT_DIM   224     // 7*MUL
#define MUL       32

#define INV_SQRT3f 0.57735026918962576451f
#define INV_SQRT2f 0.70710678118654752440f

// vector reduction: red.global.add.v4.f32 (sm_90+)
__device__ __forceinline__ void red4(float* addr, float a, float b, float c, float d) {
    asm volatile("red.global.add.v4.f32 [%0], {%1, %2, %3, %4};"
                 :: "l"(addr), "f"(a), "f"(b), "f"(c), "f"(d)
                 : "memory");
}

// streaming (evict-first) 16B load: single-use data must not occupy L2
__device__ __forceinline__ float4 ldcs4(const float4* p) { return __ldcs(p); }

__global__ void zero_out_kernel(float4* __restrict__ out, int n4) {
    int i = blockIdx.x * blockDim.x + threadIdx.x;
    int stride = gridDim.x * blockDim.x;
    float4 z = make_float4(0.f, 0.f, 0.f, 0.f);
    for (; i < n4; i += stride) out[i] = z;
}

// One edge per 8 threads; thread t owns channels [4t, 4t+4). Non-persistent.
// launch_bounds(256,4): give ptxas register headroom (<=64 regs) to front-batch
// all loads — MLP over occupancy (occ 6 CTAs measured SLOWER in R7/R8).
__global__ __launch_bounds__(256, 4)
void convtp_kernel(const float* __restrict__ nf,   // [N_NODES, 128]
                   const float* __restrict__ ang,  // [N_EDGES, 4]
                   const int* __restrict__ ei,     // [N_EDGES, 2] int32
                   const float* __restrict__ tw,   // [N_EDGES, 160]
                   float* __restrict__ out)        // [N_NODES, 224]
{
    int gid = blockIdx.x * blockDim.x + threadIdx.x;
    int e = gid >> 3;
    int t = gid & 7;
    if (e >= N_EDGES) return;

    // edge index — single-use stream, evict-first
    int2 se = __ldcs(((const int2*)ei) + e);
    int src = se.x;
    int dst = se.y;

    // angular — single-use stream, evict-first
    float4 y = ldcs4(((const float4*)ang) + e);

    // gather node features: default read-only caching (R3-proven best)
    const float4* hp = (const float4*)(nf + (long long)src * IN_DIM);
    float4 h0v = __ldg(hp + t);
    float4 hav = __ldg(hp + 8  + t);
    float4 hbv = __ldg(hp + 16 + t);
    float4 hcv = __ldg(hp + 24 + t);

    // weights — 512MB single-use stream, evict-first
    const float4* wp = (const float4*)(tw + (long long)e * W_DIM);
    float4 w0v = ldcs4(wp + t);
    float4 w1v = ldcs4(wp + 8  + t);
    float4 w2v = ldcs4(wp + 16 + t);
    float4 w3v = ldcs4(wp + 24 + t);
    float4 w4v = ldcs4(wp + 32 + t);

    const float y0  = y.x;
    const float y1x = y.y, y1y = y.z, y1z = y.w;

    const float* h0 = (const float*)&h0v;
    const float* ha = (const float*)&hav;
    const float* hb = (const float*)&hbv;
    const float* hc = (const float*)&hcv;
    const float* w0 = (const float*)&w0v;
    const float* w1 = (const float*)&w1v;
    const float* w2 = (const float*)&w2v;
    const float* w3 = (const float*)&w3v;
    const float* w4 = (const float*)&w4v;

    float r0[4], o1o0[4], o1o1[4], o1o2[4], o1e0[4], o1e1[4], o1e2[4];

    #pragma unroll
    for (int j = 0; j < 4; j++) {
        float H0 = h0[j];
        float A = ha[j], B = hb[j], C = hc[j];   // h1[0..2]
        float dot = A * y1x + B * y1y + C * y1z;

        r0[j]   = w0[j] * H0 * y0 + w3[j] * (INV_SQRT3f * dot);

        o1o0[j] = w1[j] * H0 * y1x + w2[j] * A * y0;
        o1o1[j] = w1[j] * H0 * y1y + w2[j] * B * y0;
        o1o2[j] = w1[j] * H0 * y1z + w2[j] * C * y0;

        float cr0 = B * y1z - C * y1y;
        float cr1 = C * y1x - A * y1z;
        float cr2 = A * y1y - B * y1x;
        float s = INV_SQRT2f;
        o1e0[j] = w4[j] * (s * cr0);
        o1e1[j] = w4[j] * (s * cr1);
        o1e2[j] = w4[j] * (s * cr2);
    }

    float* op = out + (long long)dst * OUT_DIM + 4 * t;
    red4(op,             r0[0],   r0[1],   r0[2],   r0[3]);
    red4(op + MUL,       o1o0[0], o1o0[1], o1o0[2], o1o0[3]);
    red4(op + 2 * MUL,   o1o1[0], o1o1[1], o1o1[2], o1o1[3]);
    red4(op + 3 * MUL,   o1o2[0], o1o2[1], o1o2[2], o1o2[3]);
    red4(op + 4 * MUL,   o1e0[0], o1e0[1], o1e0[2], o1e0[3]);
    red4(op + 5 * MUL,   o1e1[0], o1e1[1], o1e1[2], o1e1[3]);
    red4(op + 6 * MUL,   o1e2[0], o1e2[1], o1e2[2], o1e2[3]);
}

extern "C" void kernel_launch(void* const* d_in, const int* in_sizes, int n_in,
                              void* d_out, int out_size) {
    const float* nf  = (const float*)d_in[0];   // node_features
    const float* ang = (const float*)d_in[1];   // edge_angular
    const int*   ei  = (const int*)d_in[2];     // edge_index (int32)
    const float* tw  = (const float*)d_in[3];   // tp_weights
    float* out = (float*)d_out;

    // zero the (poisoned) output — vectorized
    int n4 = out_size / 4;
    int zgrid = (n4 + 255) / 256;
    if (zgrid > 2368) zgrid = 2368;
    zero_out_kernel<<<zgrid, 256>>>((float4*)out, n4);

    // main edge kernel: 8 threads per edge, 25000 CTAs
    long long total_threads = (long long)N_EDGES * 8;
    int block = 256;
    long long grid = (total_threads + block - 1) / block;
    convtp_kernel<<<(unsigned)grid, block>>>(nf, ang, ei, tw, out);
}